// round 3
// baseline (speedup 1.0000x reference)
#include <cuda_runtime.h>
#include <cuda_bf16.h>
#include <cstdint>
#include <math.h>

// Problem dims (fixed by the dataset)
#define BSZ 16
#define QQ  300
#define NC  81
#define HH  64
#define WWD 64
#define TT  400
#define HM  128
#define PP  (BSZ*QQ)     // 4800
#define HWX (HH*WWD)     // 4096

// ---------------- scratch (device globals; no allocation allowed) -------------
__device__ __align__(16) __nv_bfloat16 g_A1[(size_t)PP*HWX];   // logits bf16
__device__ __align__(16) __nv_bfloat16 g_A2[(size_t)PP*HWX];   // sigmoid bf16
__device__ __align__(16) __nv_bfloat16 g_tm[(size_t)TT*HWX];   // resized targets bf16
__device__ float g_tsum[TT];
__device__ float g_snp[PP];     // sum log_sigmoid(-m)
__device__ float g_psum[PP];    // sum sigmoid(m)
__device__ float g_prob[(size_t)PP*NC];
__device__ int   g_lab[TT];     // decoded labels (robust to int32/int64 input)

// ---------------- helpers -----------------------------------------------------
__device__ __forceinline__ float block_reduce_sum(float v, float* sh) {
    int lane = threadIdx.x & 31, w = threadIdx.x >> 5;
#pragma unroll
    for (int o = 16; o; o >>= 1) v += __shfl_down_sync(0xffffffffu, v, o);
    if (lane == 0) sh[w] = v;
    __syncthreads();
    if (w == 0) {
        v = (lane < 8) ? sh[lane] : 0.f;
#pragma unroll
        for (int o = 4; o; o >>= 1) v += __shfl_down_sync(0xffffffffu, v, o);
    }
    return v;  // valid on thread 0
}

// 4-tap antialiased linear resize weights for 128 -> 64 (jax.image.resize semantics)
__device__ __forceinline__ void taps64(int i, int& j0, float w[4]) {
    if (i == 0)       { j0 = 0;   w[0] = 3.f/7.f; w[1] = 3.f/7.f; w[2] = 1.f/7.f; w[3] = 0.f; }
    else if (i == 63) { j0 = 124; w[0] = 0.f;     w[1] = 1.f/7.f; w[2] = 3.f/7.f; w[3] = 3.f/7.f; }
    else              { j0 = 2*i - 1; w[0] = 0.125f; w[1] = 0.375f; w[2] = 0.375f; w[3] = 0.125f; }
}

// ---------------- kernel 0: decode labels (int32 vs int64 layout) --------------
__global__ void label_kernel(const void* __restrict__ labels) {
    // Inspect first 400 int32 words — in-bounds under BOTH interpretations.
    // int64 layout (little-endian, labels < 2^31): every odd word is 0.
    __shared__ int odd_nz;
    if (threadIdx.x == 0) odd_nz = 0;
    __syncthreads();
    const int* li = (const int*)labels;
    for (int i = threadIdx.x; i < TT / 2; i += blockDim.x)
        if (li[2 * i + 1] != 0) atomicOr(&odd_nz, 1);
    __syncthreads();
    bool is64 = (odd_nz == 0);
    for (int t = threadIdx.x; t < TT; t += blockDim.x)
        g_lab[t] = is64 ? (int)((const long long*)labels)[t] : li[t];
}

// ---------------- kernel 1: resize target masks + row sums --------------------
__global__ void resize_kernel(const float* __restrict__ tmasks) {
    int t = blockIdx.x;
    const float* src = tmasks + (size_t)t * HM * HM;
    __shared__ float htmp[HM][HH];   // 128 x 64, 32 KB
    for (int e = threadIdx.x; e < HM * HH; e += blockDim.x) {
        int r = e >> 6, i = e & 63;
        int j0; float w[4]; taps64(i, j0, w);
        const float* row = src + r * HM;
        htmp[r][i] = w[0]*row[j0] + w[1]*row[j0+1] + w[2]*row[j0+2] + w[3]*row[j0+3];
    }
    __syncthreads();
    float lsum = 0.f;
    for (int e = threadIdx.x; e < HWX; e += blockDim.x) {
        int o = e >> 6, i = e & 63;
        int j0; float w[4]; taps64(o, j0, w);
        float v = w[0]*htmp[j0][i] + w[1]*htmp[j0+1][i] + w[2]*htmp[j0+2][i] + w[3]*htmp[j0+3][i];
        g_tm[(size_t)t * HWX + e] = __float2bfloat16(v);
        lsum += v;
    }
    __syncthreads();
    __shared__ float shred[8];
    float tot = block_reduce_sum(lsum, shred);
    if (threadIdx.x == 0) g_tsum[t] = tot;
}

// ---------------- kernel 2: prep predictions (bf16 + row stats) ---------------
__global__ void prep_kernel(const float* __restrict__ masks) {
    int p = blockIdx.x, tid = threadIdx.x;
    const float4* src = (const float4*)(masks + (size_t)p * HWX);
    __nv_bfloat162* d1 = (__nv_bfloat162*)(g_A1 + (size_t)p * HWX);
    __nv_bfloat162* d2 = (__nv_bfloat162*)(g_A2 + (size_t)p * HWX);
    float accn = 0.f, accs = 0.f;
    for (int i = tid; i < HWX / 4; i += 256) {
        float4 v = src[i];
        float m[4] = {v.x, v.y, v.z, v.w};
        float s[4];
#pragma unroll
        for (int j = 0; j < 4; ++j) {
            s[j] = 1.f / (1.f + expf(-m[j]));
            // log_sigmoid(-m) = -(max(m,0) + log1p(exp(-|m|)))
            accn -= (fmaxf(m[j], 0.f) + log1pf(expf(-fabsf(m[j]))));
            accs += s[j];
        }
        __nv_bfloat162 a, b;
        a.x = __float2bfloat16(m[0]); a.y = __float2bfloat16(m[1]);
        b.x = __float2bfloat16(m[2]); b.y = __float2bfloat16(m[3]);
        d1[2*i] = a; d1[2*i + 1] = b;
        a.x = __float2bfloat16(s[0]); a.y = __float2bfloat16(s[1]);
        b.x = __float2bfloat16(s[2]); b.y = __float2bfloat16(s[3]);
        d2[2*i] = a; d2[2*i + 1] = b;
    }
    __shared__ float sh1[8], sh2[8];
    float tn = block_reduce_sum(accn, sh1);
    __syncthreads();
    float ts = block_reduce_sum(accs, sh2);
    if (tid == 0) { g_snp[p] = tn; g_psum[p] = ts; }
}

// ---------------- kernel 3: softmax probs -------------------------------------
__global__ void prob_kernel(const float* __restrict__ logits) {
    int p = blockIdx.x, tid = threadIdx.x;
    __shared__ float sh[128];
    float x = (tid < NC) ? logits[(size_t)p * NC + tid] : -1e30f;
    sh[tid] = x; __syncthreads();
    for (int s = 64; s > 0; s >>= 1) { if (tid < s) sh[tid] = fmaxf(sh[tid], sh[tid + s]); __syncthreads(); }
    float mx = sh[0]; __syncthreads();
    float e = (tid < NC) ? expf(x - mx) : 0.f;
    sh[tid] = e; __syncthreads();
    for (int s = 64; s > 0; s >>= 1) { if (tid < s) sh[tid] += sh[tid + s]; __syncthreads(); }
    float inv = 1.f / sh[0];
    if (tid < NC) g_prob[(size_t)p * NC + tid] = e * inv;
}

// ---------------- kernel 4: dual GEMM + fused cost epilogue -------------------
#define BM 128
#define BN 80
#define BK 32
#define SAK 40   // padded K stride in bf16 elems (80B rows, conflict-free frag loads)

struct TInfo {
    float cx, cy, w, h, x0, y0, x1, y1, area, tsum;
    int lab, pad;
};

#define SMEM_BYTES ((2*BM*SAK + 2*BM*SAK + 2*BN*SAK) * 2 + BN * (int)sizeof(TInfo))

__device__ __forceinline__ void cpa16(void* dst, const void* src, bool v) {
    uint32_t d = (uint32_t)__cvta_generic_to_shared(dst);
    int n = v ? 16 : 0;
    asm volatile("cp.async.cg.shared.global [%0], [%1], 16, %2;\n" :: "r"(d), "l"(src), "r"(n));
}
__device__ __forceinline__ void cpcommit() { asm volatile("cp.async.commit_group;\n"); }
__device__ __forceinline__ void cpwaitall() { asm volatile("cp.async.wait_all;\n"); }

__device__ __forceinline__ void mma16816(float c[4], const uint32_t a[4], const uint32_t b[2]) {
    asm volatile(
        "mma.sync.aligned.m16n8k16.row.col.f32.bf16.bf16.f32 "
        "{%0,%1,%2,%3}, {%4,%5,%6,%7}, {%8,%9}, {%0,%1,%2,%3};\n"
        : "+f"(c[0]), "+f"(c[1]), "+f"(c[2]), "+f"(c[3])
        : "r"(a[0]), "r"(a[1]), "r"(a[2]), "r"(a[3]), "r"(b[0]), "r"(b[1]));
}

__global__ void __launch_bounds__(256) gemm_kernel(
    const float* __restrict__ pboxes, const float* __restrict__ tboxes,
    float* __restrict__ out) {
    extern __shared__ char smem_raw[];
    __nv_bfloat16* sA1 = (__nv_bfloat16*)smem_raw;       // 2*BM*SAK
    __nv_bfloat16* sA2 = sA1 + 2 * BM * SAK;             // 2*BM*SAK
    __nv_bfloat16* sB  = sA2 + 2 * BM * SAK;             // 2*BN*SAK
    TInfo* sT = (TInfo*)(sB + 2 * BN * SAK);

    int tid = threadIdx.x;
    int lane = tid & 31, warp = tid >> 5;
    int m0 = blockIdx.y * BM, n0 = blockIdx.x * BN;
    int wr = (warp >> 1) * 32;   // warp row offset (4 warps along M)
    int wc = (warp & 1) * 40;    // warp col offset (2 warps along N)

    if (tid < BN) {
        int t = n0 + tid;
        float4 tb = *(const float4*)(tboxes + 4 * t);
        TInfo ti;
        ti.cx = tb.x; ti.cy = tb.y; ti.w = tb.z; ti.h = tb.w;
        ti.x0 = tb.x - 0.5f * tb.z; ti.y0 = tb.y - 0.5f * tb.w;
        ti.x1 = tb.x + 0.5f * tb.z; ti.y1 = tb.y + 0.5f * tb.w;
        ti.area = tb.z * tb.w;
        ti.tsum = g_tsum[t];
        ti.lab = g_lab[t];
        ti.pad = 0;
        sT[tid] = ti;
    }

    float acc[2][2][5][4];
#pragma unroll
    for (int a = 0; a < 2; ++a)
#pragma unroll
        for (int b = 0; b < 2; ++b)
#pragma unroll
            for (int c = 0; c < 5; ++c)
#pragma unroll
                for (int d = 0; d < 4; ++d) acc[a][b][c][d] = 0.f;

    auto loadStage = [&](int st, int k0) {
        __nv_bfloat16* dA1 = sA1 + st * BM * SAK;
        __nv_bfloat16* dA2 = sA2 + st * BM * SAK;
        __nv_bfloat16* dB  = sB  + st * BN * SAK;
        for (int c = tid; c < BM * 4; c += 256) {
            int r = c >> 2, s = c & 3;
            int p = m0 + r;
            bool v = p < PP;
            size_t off = (size_t)p * HWX + k0 + s * 8;
            cpa16(dA1 + r * SAK + s * 8, g_A1 + off, v);
            cpa16(dA2 + r * SAK + s * 8, g_A2 + off, v);
        }
        for (int c = tid; c < BN * 4; c += 256) {
            int r = c >> 2, s = c & 3;
            cpa16(dB + r * SAK + s * 8, g_tm + (size_t)(n0 + r) * HWX + k0 + s * 8, true);
        }
    };

    loadStage(0, 0);
    cpcommit();
    int st = 0;
    const int KT = HWX / BK;  // 128
    for (int kt = 0; kt < KT; ++kt) {
        cpwaitall();
        __syncthreads();
        if (kt + 1 < KT) { loadStage(st ^ 1, (kt + 1) * BK); cpcommit(); }

        const __nv_bfloat16* A1s = sA1 + st * BM * SAK;
        const __nv_bfloat16* A2s = sA2 + st * BM * SAK;
        const __nv_bfloat16* Bs  = sB  + st * BN * SAK;
#pragma unroll
        for (int ks = 0; ks < 2; ++ks) {
            int cb = ks * 16 + 2 * (lane & 3);
            uint32_t af[2][2][4];
#pragma unroll
            for (int mi = 0; mi < 2; ++mi) {
                int r = wr + mi * 16 + (lane >> 2);
                af[0][mi][0] = *(const uint32_t*)(A1s + r * SAK + cb);
                af[0][mi][1] = *(const uint32_t*)(A1s + (r + 8) * SAK + cb);
                af[0][mi][2] = *(const uint32_t*)(A1s + r * SAK + cb + 8);
                af[0][mi][3] = *(const uint32_t*)(A1s + (r + 8) * SAK + cb + 8);
                af[1][mi][0] = *(const uint32_t*)(A2s + r * SAK + cb);
                af[1][mi][1] = *(const uint32_t*)(A2s + (r + 8) * SAK + cb);
                af[1][mi][2] = *(const uint32_t*)(A2s + r * SAK + cb + 8);
                af[1][mi][3] = *(const uint32_t*)(A2s + (r + 8) * SAK + cb + 8);
            }
            uint32_t bf[5][2];
#pragma unroll
            for (int ni = 0; ni < 5; ++ni) {
                int n = wc + ni * 8 + (lane >> 2);
                bf[ni][0] = *(const uint32_t*)(Bs + n * SAK + cb);
                bf[ni][1] = *(const uint32_t*)(Bs + n * SAK + cb + 8);
            }
#pragma unroll
            for (int s2 = 0; s2 < 2; ++s2)
#pragma unroll
                for (int mi = 0; mi < 2; ++mi)
#pragma unroll
                    for (int ni = 0; ni < 5; ++ni)
                        mma16816(acc[s2][mi][ni], af[s2][mi], bf[ni]);
        }
        __syncthreads();
        st ^= 1;
    }

    // ---- fused cost epilogue ----
    const float inv_hw = 1.0f / (float)HWX;
#pragma unroll
    for (int mi = 0; mi < 2; ++mi) {
#pragma unroll
        for (int rh = 0; rh < 2; ++rh) {
            int p = m0 + wr + mi * 16 + (lane >> 2) + rh * 8;
            if (p >= PP) continue;
            float snp_p = g_snp[p], psum_p = g_psum[p];
            float4 pb = *(const float4*)(pboxes + 4 * p);
            float px0 = pb.x - 0.5f * pb.z, py0 = pb.y - 0.5f * pb.w;
            float px1 = pb.x + 0.5f * pb.z, py1 = pb.y + 0.5f * pb.w;
            float parea = pb.z * pb.w;
            const float* prow = g_prob + (size_t)p * NC;
#pragma unroll
            for (int ni = 0; ni < 5; ++ni) {
#pragma unroll
                for (int cc = 0; cc < 2; ++cc) {
                    int tl = wc + ni * 8 + 2 * (lane & 3) + cc;
                    TInfo ti = sT[tl];
                    float d1 = acc[0][mi][ni][rh * 2 + cc];
                    float d2 = acc[1][mi][ni][rh * 2 + cc];
                    float l1 = fabsf(pb.x - ti.cx) + fabsf(pb.y - ti.cy)
                             + fabsf(pb.z - ti.w) + fabsf(pb.w - ti.h);
                    float ix0 = fmaxf(px0, ti.x0), iy0 = fmaxf(py0, ti.y0);
                    float ix1 = fminf(px1, ti.x1), iy1 = fminf(py1, ti.y1);
                    float inter = fmaxf(ix1 - ix0, 0.f) * fmaxf(iy1 - iy0, 0.f);
                    float uni = parea + ti.area - inter;
                    float iou = inter / uni;
                    float ex0 = fminf(px0, ti.x0), ey0 = fminf(py0, ti.y0);
                    float ex1 = fmaxf(px1, ti.x1), ey1 = fmaxf(py1, ti.y1);
                    float enc = fmaxf(ex1 - ex0, 0.f) * fmaxf(ey1 - ey0, 0.f);
                    float giou = iou - (enc - uni) / enc;
                    float cmask = -(d1 + snp_p) * inv_hw;
                    float cdice = 1.f - (2.f * d2 + 1e-5f) / (psum_p + ti.tsum + 1e-5f);
                    float ccls = -prow[ti.lab];
                    out[(size_t)p * TT + n0 + tl] =
                        5.f * l1 - 2.f * giou + 2.f * ccls + 5.f * cmask + 5.f * cdice;
                }
            }
        }
    }
}

// ---------------- launch ------------------------------------------------------
extern "C" void kernel_launch(void* const* d_in, const int* in_sizes, int n_in,
                              void* d_out, int out_size) {
    const float* pred_logits = (const float*)d_in[0];
    const float* pred_boxes  = (const float*)d_in[1];
    const float* pred_masks  = (const float*)d_in[2];
    const float* tgt_boxes   = (const float*)d_in[3];
    const float* tgt_masks   = (const float*)d_in[4];
    const void*  tgt_labels  = (const void*)d_in[5];
    float* out = (float*)d_out;

    label_kernel<<<1, 256>>>(tgt_labels);
    resize_kernel<<<TT, 256>>>(tgt_masks);
    prep_kernel<<<PP, 256>>>(pred_masks);
    prob_kernel<<<PP, 128>>>(pred_logits);

    cudaFuncSetAttribute(gemm_kernel, cudaFuncAttributeMaxDynamicSharedMemorySize, SMEM_BYTES);
    gemm_kernel<<<dim3(5, (PP + BM - 1) / BM), 256, SMEM_BYTES>>>(
        pred_boxes, tgt_boxes, out);
}